// round 2
// baseline (speedup 1.0000x reference)
#include <cuda_runtime.h>
#include <cuda_bf16.h>

// Problem constants
#define NLAT   8192     // latents per tensor
#define NSMP   2048     // samples per tensor
#define ES     64       // state embedding dim
#define EA     32       // action embedding dim
#define TAILK  4        // selection_tail_size == pushing_sample_size
#define FARK   64       // far_sample_count
#define NSL    32       // latent slices
#define LPS    (NLAT / NSL)   // 256 latents per slice
#define TPB    256      // threads per block (each thread = one sample)
#define SCHUNK (NSMP / TPB)   // 8 sample chunks

#define FLT_BIG 3.402823466e+38f

#define ADD_F32X2(out, a, b) \
    asm("add.rn.f32x2 %0, %1, %2;" : "=l"(out) : "l"(a), "l"(b))

// ---------------- scratch (device globals; no allocation allowed) ----------
__device__ float g_pt4[2][NSL * NSMP * 4];   // [tensor][slice][sample][4]
__device__ float g_tail[2][NSMP];
__device__ float g_sq[2][NSMP];
__device__ float g_selsq[2][NSMP];
__device__ float g_sizes[2];

// branchless sorted insert: keep m0<=m1<=m2<=m3 the 4 smallest seen (FMNMX, alu pipe)
__device__ __forceinline__ void ins4(float d, float& m0, float& m1, float& m2, float& m3) {
    float lo, hi;
    lo = fminf(m0, d);  hi = fmaxf(m0, d);  m0 = lo;
    lo = fminf(m1, hi); hi = fmaxf(m1, hi); m1 = lo;
    lo = fminf(m2, hi); hi = fmaxf(m2, hi); m2 = lo;
    m3 = fminf(m3, hi);
}

// ---------------- size loss: mean(relu(L1norm - 1)^2) over 8192 rows -------
template<int E>
__device__ __forceinline__ float size_accum(const float* __restrict__ lat, int tid) {
    float acc = 0.0f;
    for (int r = tid; r < NLAT; r += TPB) {
        const float* row = lat + r * E;
        float a0 = 0.f, a1 = 0.f, a2 = 0.f, a3 = 0.f;
        #pragma unroll
        for (int k = 0; k < E; k += 4) {
            float4 v = *(const float4*)(row + k);
            a0 += fabsf(v.x); a1 += fabsf(v.y); a2 += fabsf(v.z); a3 += fabsf(v.w);
        }
        float n = (a0 + a1) + (a2 + a3);
        float viol = fmaxf(n - 1.0f, 0.0f);   // STATE/ACTION_SPACE_SIZE == 1.0
        acc += viol * viol;
    }
    return acc;
}

__global__ void size_loss_kernel(const float* __restrict__ lat_s,
                                 const float* __restrict__ lat_a) {
    __shared__ float red[TPB];
    const int tid = threadIdx.x;
    float acc = (blockIdx.x == 0) ? size_accum<ES>(lat_s, tid)
                                  : size_accum<EA>(lat_a, tid);
    red[tid] = acc;
    __syncthreads();
    for (int st = TPB / 2; st > 0; st >>= 1) {
        if (tid < st) red[tid] += red[tid + st];
        __syncthreads();
    }
    if (tid == 0) g_sizes[blockIdx.x] = red[0] / (float)NLAT;
}

// ---------------- coverage partial top-4 (packed f32x2 inner loop) ---------
// Each thread owns one sample (row packed into u64 pairs in registers) and
// scans this block's latent slice streamed through smem tiles that were
// NEGATED at load time, so diff = q + (-lat) is one add.rn.f32x2 (fma pipe),
// abs is a 64-bit AND (2x LOP3, alu pipe), accumulate is add.rn.f32x2.
template<int E, int TN, int SEL>
__device__ __forceinline__ void cov_body(const float* __restrict__ samples,
                                         const float* __restrict__ latents,
                                         float* tile) {
    const int tid  = threadIdx.x;
    const int s    = blockIdx.x * TPB + tid;
    const int lat0 = blockIdx.y * LPS;

    // sample row -> packed u64 registers (adjacent float pairs)
    unsigned long long qp[E / 2];
    {
        const ulonglong2* qsrc = (const ulonglong2*)(samples + s * E);
        #pragma unroll
        for (int k = 0; k < E / 4; k++) {
            ulonglong2 v = qsrc[k];
            qp[2 * k] = v.x; qp[2 * k + 1] = v.y;
        }
    }

    float m0 = FLT_BIG, m1 = FLT_BIG, m2 = FLT_BIG, m3 = FLT_BIG;

    for (int t0 = 0; t0 < LPS; t0 += TN) {
        __syncthreads();
        // cooperative tile load with sign-flip (pre-negate latents)
        const ulonglong2* src = (const ulonglong2*)(latents + (lat0 + t0) * E);
        ulonglong2* dst = (ulonglong2*)tile;
        #pragma unroll
        for (int i = tid; i < TN * E / 4; i += TPB) {
            ulonglong2 v = src[i];
            v.x ^= 0x8000000080000000ULL;
            v.y ^= 0x8000000080000000ULL;
            dst[i] = v;
        }
        __syncthreads();

        #pragma unroll 1
        for (int n = 0; n < TN; n++) {
            const ulonglong2* lr = (const ulonglong2*)(tile + n * E); // broadcast LDS.128
            unsigned long long a0 = 0ULL, a1 = 0ULL, a2 = 0ULL, a3 = 0ULL;
            #pragma unroll
            for (int k = 0; k < E / 4; k++) {
                ulonglong2 v = lr[k];
                unsigned long long d0, d1;
                ADD_F32X2(d0, qp[2 * k],     v.x);   // q - lat (fma pipe)
                ADD_F32X2(d1, qp[2 * k + 1], v.y);
                d0 &= 0x7fffffff7fffffffULL;         // |.| (2x LOP3, alu pipe)
                d1 &= 0x7fffffff7fffffffULL;
                if (k & 1) { ADD_F32X2(a2, a2, d0); ADD_F32X2(a3, a3, d1); }
                else       { ADD_F32X2(a0, a0, d0); ADD_F32X2(a1, a1, d1); }
            }
            ADD_F32X2(a0, a0, a2);
            ADD_F32X2(a1, a1, a3);
            ADD_F32X2(a0, a0, a1);
            float d = __uint_as_float((unsigned)a0)
                    + __uint_as_float((unsigned)(a0 >> 32));
            ins4(d, m0, m1, m2, m3);
        }
    }

    // layout [slice][sample][4] -> coalesced float4 store & merge reads
    *(float4*)(&g_pt4[SEL][(blockIdx.y * NSMP + s) * 4]) = make_float4(m0, m1, m2, m3);
}

// grid: (SCHUNK, NSL, 2) — z selects tensor; one fused launch packs waves.
__global__ void __launch_bounds__(TPB, 2)
cov_partial_kernel(const float* __restrict__ smp_s, const float* __restrict__ lat_s,
                   const float* __restrict__ smp_a, const float* __restrict__ lat_a) {
    __shared__ __align__(16) float tile[4096];   // 16 KB, both paths
    if (blockIdx.z == 0) cov_body<ES, 64, 0>(smp_s, lat_s, tile);
    else                 cov_body<EA, 128, 1>(smp_a, lat_a, tile);
}

// ---------------- merge partial top-4 across slices ------------------------
__global__ void cov_merge_kernel() {
    const int sel = blockIdx.y;
    const int s   = blockIdx.x * TPB + threadIdx.x;
    float m0 = FLT_BIG, m1 = FLT_BIG, m2 = FLT_BIG, m3 = FLT_BIG;
    const float* base = g_pt4[sel];
    #pragma unroll 4
    for (int sl = 0; sl < NSL; sl++) {
        float4 v = *(const float4*)(base + (sl * NSMP + s) * 4);
        ins4(v.x, m0, m1, m2, m3);
        ins4(v.y, m0, m1, m2, m3);
        ins4(v.z, m0, m1, m2, m3);
        ins4(v.w, m0, m1, m2, m3);
    }
    g_tail[sel][s] = 0.25f * ((m0 + m1) + (m2 + m3));
    g_sq[sel][s]   = (m0 * m0 + m1 * m1) + (m2 * m2 + m3 * m3);
}

// ---------------- rank: select top-64 tails (stable, matching lax.top_k) ---
__global__ void rank_select_kernel() {
    __shared__ float t[NSMP];
    const int sel = blockIdx.y;
    const int tid = threadIdx.x;
    for (int i = tid; i < NSMP; i += TPB) t[i] = g_tail[sel][i];
    __syncthreads();

    const int i  = blockIdx.x * TPB + tid;
    const float ti = t[i];
    int cnt = 0;
    #pragma unroll 8
    for (int j = 0; j < NSMP; j++) {
        float tj = t[j];
        cnt += (tj > ti) || (tj == ti && j < i);
    }
    g_selsq[sel][i] = (cnt < FARK) ? g_sq[sel][i] : 0.0f;
}

// ---------------- final combine (deterministic fixed-order reduce) ---------
__global__ void combine_kernel(float* __restrict__ out) {
    __shared__ float red[TPB];
    const int tid = threadIdx.x;
    float acc = 0.0f;
    for (int i = tid; i < NSMP; i += TPB)
        acc += g_selsq[0][i] + g_selsq[1][i];
    red[tid] = acc;
    __syncthreads();
    for (int st = TPB / 2; st > 0; st >>= 1) {
        if (tid < st) red[tid] += red[tid + st];
        __syncthreads();
    }
    if (tid == 0)
        out[0] = g_sizes[0] + g_sizes[1] + red[0] / (float)(FARK * TAILK);
}

// ---------------- launch ----------------------------------------------------
extern "C" void kernel_launch(void* const* d_in, const int* in_sizes, int n_in,
                              void* d_out, int out_size) {
    const float* lat_s = (const float*)d_in[0];   // latent_states   [8192,64]
    const float* lat_a = (const float*)d_in[1];   // latent_actions  [8192,32]
    const float* smp_s = (const float*)d_in[2];   // state samples   [2048,64]
    const float* smp_a = (const float*)d_in[3];   // action samples  [2048,32]
    float* out = (float*)d_out;

    size_loss_kernel<<<2, TPB>>>(lat_s, lat_a);
    cov_partial_kernel<<<dim3(SCHUNK, NSL, 2), TPB>>>(smp_s, lat_s, smp_a, lat_a);
    cov_merge_kernel<<<dim3(SCHUNK, 2), TPB>>>();
    rank_select_kernel<<<dim3(SCHUNK, 2), TPB>>>();
    combine_kernel<<<1, TPB>>>(out);
}

// round 3
// speedup vs baseline: 1.5599x; 1.5599x over previous
#include <cuda_runtime.h>
#include <cuda_bf16.h>

// Problem constants
#define NLAT   8192
#define NSMP   2048
#define ES     64
#define EA     32
#define TAILK  4
#define FARK   64
#define TPB    256
#define SCHUNK (NSMP / TPB)     // 8 sample chunks
#define NSL_S  49               // latent slices, states  (8*49 blocks)
#define NSL_A  25               // latent slices, actions (8*25 blocks) -> 592 total = 2 full waves
#define FLT_BIG 3.402823466e+38f

// ---------------- scratch (device globals; no allocation allowed) ----------
__device__ float g_pt4_s[NSL_S * NSMP * 4];   // [slice][sample][4]
__device__ float g_pt4_a[NSL_A * NSMP * 4];
__device__ float g_tail[2][NSMP];
__device__ float g_sq[2][NSMP];
__device__ int   g_cnt[2][NSMP];
__device__ float g_size_part[16];

// branchless sorted insert: keep m0<=m1<=m2<=m3 smallest (FMNMX, alu pipe)
__device__ __forceinline__ void ins4(float d, float& m0, float& m1, float& m2, float& m3) {
    float lo, hi;
    lo = fminf(m0, d);  hi = fmaxf(m0, d);  m0 = lo;
    lo = fminf(m1, hi); hi = fmaxf(m1, hi); m1 = lo;
    lo = fminf(m2, hi); hi = fmaxf(m2, hi); m2 = lo;
    m3 = fminf(m3, hi);
}

// ---------------- size loss partials: relu(L1norm - 1)^2 -------------------
template<int E>
__device__ __forceinline__ float size_accum(const float* __restrict__ lat, int r0, int tid) {
    float acc = 0.0f;
    for (int r = r0 + tid; r < r0 + NLAT / 8; r += TPB) {
        const float* row = lat + r * E;
        float a0 = 0.f, a1 = 0.f, a2 = 0.f, a3 = 0.f;
        #pragma unroll
        for (int k = 0; k < E; k += 4) {
            float4 v = *(const float4*)(row + k);
            a0 += fabsf(v.x); a1 += fabsf(v.y); a2 += fabsf(v.z); a3 += fabsf(v.w);
        }
        float n = (a0 + a1) + (a2 + a3);
        float viol = fmaxf(n - 1.0f, 0.0f);
        acc += viol * viol;
    }
    return acc;
}

__global__ void size_loss_kernel(const float* __restrict__ lat_s,
                                 const float* __restrict__ lat_a) {
    __shared__ float red[TPB];
    const int tid = threadIdx.x;
    const int b = blockIdx.x;                 // 0..15
    float acc = (b < 8) ? size_accum<ES>(lat_s, b * (NLAT / 8), tid)
                        : size_accum<EA>(lat_a, (b - 8) * (NLAT / 8), tid);
    red[tid] = acc;
    __syncthreads();
    for (int st = TPB / 2; st > 0; st >>= 1) {
        if (tid < st) red[tid] += red[tid + st];
        __syncthreads();
    }
    if (tid == 0) g_size_part[b] = red[0];
}

// ---------------- coverage partial top-4 (FFMA-imm inner loop) -------------
// d  = fmaf(lat, -0.5, q*0.5)  -> FFMA Rd, Rlat, -0.5, Rqh   (imm, rt=1)
// acc= fmaf(|d|, 2.0, acc)     -> FFMA Racc, |Rd|, 2.0, Racc (imm, rt=1)
// Exact: fl((q-l)/2)*2 == fl(q-l); bitwise identical to the FADD chain.
template<int E, int TN, int NSL>
__device__ __forceinline__ void cov_body(const float* __restrict__ samples,
                                         const float* __restrict__ latents,
                                         int slice, float* tile, float* out4) {
    const int tid = threadIdx.x;
    const int s   = blockIdx.x * TPB + tid;

    constexpr int base = NLAT / NSL;
    constexpr int rem  = NLAT % NSL;
    const int start = slice * base + (slice < rem ? slice : rem);
    const int len   = base + (slice < rem ? 1 : 0);

    // sample row * 0.5 -> registers
    float qh[E];
    #pragma unroll
    for (int k = 0; k < E; k += 4) {
        float4 v = *(const float4*)(samples + s * E + k);
        qh[k] = 0.5f * v.x; qh[k + 1] = 0.5f * v.y;
        qh[k + 2] = 0.5f * v.z; qh[k + 3] = 0.5f * v.w;
    }

    float m0 = FLT_BIG, m1 = FLT_BIG, m2 = FLT_BIG, m3 = FLT_BIG;

    for (int t0 = 0; t0 < len; t0 += TN) {
        const int tn = (len - t0 < TN) ? (len - t0) : TN;
        __syncthreads();
        const float4* src = (const float4*)(latents + (start + t0) * E);
        float4* dst = (float4*)tile;
        for (int i = tid; i < tn * E / 4; i += TPB) dst[i] = src[i];
        __syncthreads();

        #pragma unroll 1
        for (int n = 0; n < tn; n++) {
            const float4* lr = (const float4*)(tile + n * E);  // broadcast LDS.128
            float a0 = 0.f, a1 = 0.f, a2 = 0.f, a3 = 0.f;
            #pragma unroll
            for (int k = 0; k < E / 4; k++) {
                float4 v = lr[k];
                float d0 = fmaf(v.x, -0.5f, qh[4 * k]);
                float d1 = fmaf(v.y, -0.5f, qh[4 * k + 1]);
                float d2 = fmaf(v.z, -0.5f, qh[4 * k + 2]);
                float d3 = fmaf(v.w, -0.5f, qh[4 * k + 3]);
                a0 = fmaf(fabsf(d0), 2.0f, a0);
                a1 = fmaf(fabsf(d1), 2.0f, a1);
                a2 = fmaf(fabsf(d2), 2.0f, a2);
                a3 = fmaf(fabsf(d3), 2.0f, a3);
            }
            float d = (a0 + a1) + (a2 + a3);
            ins4(d, m0, m1, m2, m3);
        }
    }
    *(float4*)(out4 + (slice * NSMP + s) * 4) = make_float4(m0, m1, m2, m3);
}

// grid: (SCHUNK, NSL_S + NSL_A). y < NSL_S -> states.
__global__ void __launch_bounds__(TPB, 2)
cov_partial_kernel(const float* __restrict__ smp_s, const float* __restrict__ lat_s,
                   const float* __restrict__ smp_a, const float* __restrict__ lat_a) {
    __shared__ __align__(16) float tile[4096];   // 16 KB
    const int y = blockIdx.y;
    if (y < NSL_S) cov_body<ES, 64, NSL_S>(smp_s, lat_s, y, tile, g_pt4_s);
    else           cov_body<EA, 128, NSL_A>(smp_a, lat_a, y - NSL_S, tile, g_pt4_a);
}

// ---------------- merge partial top-4 across slices ------------------------
// 4 threads per sample (each covers slices sub, sub+4, ...), shfl combine.
// grid: (NSMP/64, 2), TPB threads.
__global__ void cov_merge_kernel() {
    const int sel = blockIdx.y;
    const int tid = threadIdx.x;
    const int s   = blockIdx.x * 64 + (tid >> 2);
    const int sub = tid & 3;
    const int nsl = sel ? NSL_A : NSL_S;
    const float* base = sel ? g_pt4_a : g_pt4_s;

    float m0 = FLT_BIG, m1 = FLT_BIG, m2 = FLT_BIG, m3 = FLT_BIG;
    for (int k = sub; k < nsl; k += 4) {
        float4 v = *(const float4*)(base + (k * NSMP + s) * 4);
        ins4(v.x, m0, m1, m2, m3);
        ins4(v.y, m0, m1, m2, m3);
        ins4(v.z, m0, m1, m2, m3);
        ins4(v.w, m0, m1, m2, m3);
    }
    #pragma unroll
    for (int off = 2; off >= 1; off >>= 1) {
        float n0 = __shfl_down_sync(0xffffffffu, m0, off);
        float n1 = __shfl_down_sync(0xffffffffu, m1, off);
        float n2 = __shfl_down_sync(0xffffffffu, m2, off);
        float n3 = __shfl_down_sync(0xffffffffu, m3, off);
        ins4(n0, m0, m1, m2, m3);
        ins4(n1, m0, m1, m2, m3);
        ins4(n2, m0, m1, m2, m3);
        ins4(n3, m0, m1, m2, m3);
    }
    if (sub == 0) {
        g_tail[sel][s] = 0.25f * ((m0 + m1) + (m2 + m3));
        g_sq[sel][s]   = (m0 * m0 + m1 * m1) + (m2 * m2 + m3 * m3);
        g_cnt[sel][s]  = 0;
    }
}

// ---------------- rank counts (stable, matching lax.top_k ties) ------------
// grid: (SCHUNK, 2, 8): z splits the j-range; integer atomic partial counts.
__global__ void rank_kernel() {
    __shared__ float tj_s[256];
    const int sel = blockIdx.y;
    const int tid = threadIdx.x;
    const int jbase = blockIdx.z * 256;
    tj_s[tid] = g_tail[sel][jbase + tid];
    __syncthreads();

    const int i  = blockIdx.x * TPB + tid;
    const int ti = __float_as_int(g_tail[sel][i]);   // positive floats: int order == fp order
    int cnt = 0;
    #pragma unroll 8
    for (int jj = 0; jj < 256; jj++) {
        int tj = __float_as_int(tj_s[jj]);
        cnt += (tj > ti) || (tj == ti && (jbase + jj) < i);
    }
    if (cnt) atomicAdd(&g_cnt[sel][i], cnt);
}

// ---------------- final combine (deterministic fixed-order reduce) ---------
__global__ void combine_kernel(float* __restrict__ out) {
    __shared__ float red[TPB];
    const int tid = threadIdx.x;
    float acc = 0.0f;
    for (int i = tid; i < NSMP; i += TPB) {
        if (g_cnt[0][i] < FARK) acc += g_sq[0][i];
        if (g_cnt[1][i] < FARK) acc += g_sq[1][i];
    }
    red[tid] = acc;
    __syncthreads();
    for (int st = TPB / 2; st > 0; st >>= 1) {
        if (tid < st) red[tid] += red[tid + st];
        __syncthreads();
    }
    if (tid == 0) {
        float ss = 0.f, sa = 0.f;
        #pragma unroll
        for (int b = 0; b < 8; b++)  ss += g_size_part[b];
        #pragma unroll
        for (int b = 8; b < 16; b++) sa += g_size_part[b];
        out[0] = ss / (float)NLAT + sa / (float)NLAT
               + red[0] / (float)(FARK * TAILK);
    }
}

// ---------------- launch ----------------------------------------------------
extern "C" void kernel_launch(void* const* d_in, const int* in_sizes, int n_in,
                              void* d_out, int out_size) {
    const float* lat_s = (const float*)d_in[0];   // latent_states   [8192,64]
    const float* lat_a = (const float*)d_in[1];   // latent_actions  [8192,32]
    const float* smp_s = (const float*)d_in[2];   // state samples   [2048,64]
    const float* smp_a = (const float*)d_in[3];   // action samples  [2048,32]
    float* out = (float*)d_out;

    size_loss_kernel<<<16, TPB>>>(lat_s, lat_a);
    cov_partial_kernel<<<dim3(SCHUNK, NSL_S + NSL_A), TPB>>>(smp_s, lat_s, smp_a, lat_a);
    cov_merge_kernel<<<dim3(NSMP / 64, 2), TPB>>>();
    rank_kernel<<<dim3(SCHUNK, 2, 8), TPB>>>();
    combine_kernel<<<1, TPB>>>(out);
}

// round 5
// speedup vs baseline: 1.7416x; 1.1165x over previous
#include <cuda_runtime.h>
#include <cuda_bf16.h>

// Problem constants
#define NLAT   8192
#define NSMP   2048
#define ES     64
#define EA     32
#define TAILK  4
#define FARK   64
#define TPB    256
#define SCHUNK (NSMP / TPB)     // 8 sample chunks
#define NSL_S  45               // latent slices, states
#define NSL_A  25               // latent slices, actions
#define NSL_Z  4                // size-loss block rows
// 8*(45+25+4) = 592 blocks = exactly 2 waves at occupancy 2
#define FLT_BIG 3.402823466e+38f

// ---------------- scratch (device globals; no allocation allowed) ----------
__device__ float g_pt4_s[NSL_S * NSMP * 4];   // [slice][sample][4]
__device__ float g_pt4_a[NSL_A * NSMP * 4];
__device__ float g_tail[2][NSMP];
__device__ float g_sq[2][NSMP];
__device__ int   g_cnt[2][NSMP];
__device__ float g_size_part[NSL_Z * 8];

// branchless sorted insert: keep m0<=m1<=m2<=m3 smallest
__device__ __forceinline__ void ins4(float d, float& m0, float& m1, float& m2, float& m3) {
    float lo, hi;
    lo = fminf(m0, d);  hi = fmaxf(m0, d);  m0 = lo;
    lo = fminf(m1, hi); hi = fmaxf(m1, hi); m1 = lo;
    lo = fminf(m2, hi); hi = fmaxf(m2, hi); m2 = lo;
    m3 = fminf(m3, hi);
}

// ---------------- size loss partials (runs inside the cov launch) ----------
template<int E>
__device__ __forceinline__ float size_accum(const float* __restrict__ lat, int r0, int nrows, int tid) {
    float acc = 0.0f;
    for (int r = r0 + tid; r < r0 + nrows; r += TPB) {
        const float* row = lat + r * E;
        float a0 = 0.f, a1 = 0.f, a2 = 0.f, a3 = 0.f;
        #pragma unroll
        for (int k = 0; k < E; k += 4) {
            float4 v = *(const float4*)(row + k);
            a0 += fabsf(v.x); a1 += fabsf(v.y); a2 += fabsf(v.z); a3 += fabsf(v.w);
        }
        float n = (a0 + a1) + (a2 + a3);
        float viol = fmaxf(n - 1.0f, 0.0f);
        acc += viol * viol;
    }
    return acc;
}

__device__ void size_body(const float* __restrict__ lat_s,
                          const float* __restrict__ lat_a, int b, float* red) {
    const int tid = threadIdx.x;
    // 32 blocks: 16 for states (512 rows each), 16 for actions (512 rows each)
    float acc = (b < 16) ? size_accum<ES>(lat_s, b * 512, 512, tid)
                         : size_accum<EA>(lat_a, (b - 16) * 512, 512, tid);
    red[tid] = acc;
    __syncthreads();
    for (int st = TPB / 2; st > 0; st >>= 1) {
        if (tid < st) red[tid] += red[tid + st];
        __syncthreads();
    }
    if (tid == 0) g_size_part[b] = red[0];
}

// ---------------- coverage partial top-4 (FFMA-imm, latent-pair unroll) ----
// d  = fmaf(lat, -0.5, q*0.5)  -> FFMA-imm rt=1
// acc= fmaf(|d|, 2.0, acc)     -> FFMA-imm rt=1; exact rescale, bit-identical
template<int E, int TN, int NSL>
__device__ __forceinline__ void cov_body(const float* __restrict__ samples,
                                         const float* __restrict__ latents,
                                         int slice, float* tile, float* out4) {
    const int tid = threadIdx.x;
    const int s   = blockIdx.x * TPB + tid;

    constexpr int base = NLAT / NSL;
    constexpr int rem  = NLAT % NSL;
    const int start = slice * base + (slice < rem ? slice : rem);
    const int len   = base + (slice < rem ? 1 : 0);

    // sample row * 0.5 -> registers (exact)
    float qh[E];
    #pragma unroll
    for (int k = 0; k < E; k += 4) {
        float4 v = *(const float4*)(samples + s * E + k);
        qh[k] = 0.5f * v.x; qh[k + 1] = 0.5f * v.y;
        qh[k + 2] = 0.5f * v.z; qh[k + 3] = 0.5f * v.w;
    }

    float m0 = FLT_BIG, m1 = FLT_BIG, m2 = FLT_BIG, m3 = FLT_BIG;

    for (int t0 = 0; t0 < len; t0 += TN) {
        const int tn = (len - t0 < TN) ? (len - t0) : TN;
        __syncthreads();
        const float4* src = (const float4*)(latents + (start + t0) * E);
        float4* dst = (float4*)tile;
        for (int i = tid; i < tn * (E / 4); i += TPB) dst[i] = src[i];
        __syncthreads();

        int n = 0;
        #pragma unroll 1
        for (; n + 2 <= tn; n += 2) {
            const float4* lrA = (const float4*)(tile + n * E);
            const float4* lrB = (const float4*)(tile + (n + 1) * E);
            float a0 = 0.f, a1 = 0.f, a2 = 0.f, a3 = 0.f;
            float b0 = 0.f, b1 = 0.f, b2 = 0.f, b3 = 0.f;
            #pragma unroll
            for (int k = 0; k < E / 4; k++) {
                float4 va = lrA[k];
                float d0 = fmaf(va.x, -0.5f, qh[4 * k]);
                float d1 = fmaf(va.y, -0.5f, qh[4 * k + 1]);
                float d2 = fmaf(va.z, -0.5f, qh[4 * k + 2]);
                float d3 = fmaf(va.w, -0.5f, qh[4 * k + 3]);
                a0 = fmaf(fabsf(d0), 2.0f, a0);
                a1 = fmaf(fabsf(d1), 2.0f, a1);
                a2 = fmaf(fabsf(d2), 2.0f, a2);
                a3 = fmaf(fabsf(d3), 2.0f, a3);
                float4 vb = lrB[k];
                float e0 = fmaf(vb.x, -0.5f, qh[4 * k]);
                float e1 = fmaf(vb.y, -0.5f, qh[4 * k + 1]);
                float e2 = fmaf(vb.z, -0.5f, qh[4 * k + 2]);
                float e3 = fmaf(vb.w, -0.5f, qh[4 * k + 3]);
                b0 = fmaf(fabsf(e0), 2.0f, b0);
                b1 = fmaf(fabsf(e1), 2.0f, b1);
                b2 = fmaf(fabsf(e2), 2.0f, b2);
                b3 = fmaf(fabsf(e3), 2.0f, b3);
            }
            float dA = (a0 + a1) + (a2 + a3);
            float dB = (b0 + b1) + (b2 + b3);
            ins4(dA, m0, m1, m2, m3);
            ins4(dB, m0, m1, m2, m3);
        }
        if (n < tn) {   // odd epilogue
            const float4* lr = (const float4*)(tile + n * E);
            float a0 = 0.f, a1 = 0.f, a2 = 0.f, a3 = 0.f;
            #pragma unroll
            for (int k = 0; k < E / 4; k++) {
                float4 v = lr[k];
                float d0 = fmaf(v.x, -0.5f, qh[4 * k]);
                float d1 = fmaf(v.y, -0.5f, qh[4 * k + 1]);
                float d2 = fmaf(v.z, -0.5f, qh[4 * k + 2]);
                float d3 = fmaf(v.w, -0.5f, qh[4 * k + 3]);
                a0 = fmaf(fabsf(d0), 2.0f, a0);
                a1 = fmaf(fabsf(d1), 2.0f, a1);
                a2 = fmaf(fabsf(d2), 2.0f, a2);
                a3 = fmaf(fabsf(d3), 2.0f, a3);
            }
            ins4((a0 + a1) + (a2 + a3), m0, m1, m2, m3);
        }
    }
    *(float4*)(out4 + (slice * NSMP + s) * 4) = make_float4(m0, m1, m2, m3);
}

// grid: (SCHUNK, NSL_S + NSL_A + NSL_Z)
__global__ void __launch_bounds__(TPB, 2)
cov_partial_kernel(const float* __restrict__ smp_s, const float* __restrict__ lat_s,
                   const float* __restrict__ smp_a, const float* __restrict__ lat_a) {
    __shared__ __align__(16) float tile[8192];   // 32 KB
    const int y = blockIdx.y;
    if (y < NSL_S)
        cov_body<ES, 128, NSL_S>(smp_s, lat_s, y, tile, g_pt4_s);
    else if (y < NSL_S + NSL_A)
        cov_body<EA, 256, NSL_A>(smp_a, lat_a, y - NSL_S, tile, g_pt4_a);
    else
        size_body(lat_s, lat_a, (y - NSL_S - NSL_A) * 8 + blockIdx.x, tile);
}

// ---------------- merge partial top-4 across slices ------------------------
// 4 threads per sample, shfl combine. grid: (NSMP/64, 2)
__global__ void cov_merge_kernel() {
    const int sel = blockIdx.y;
    const int tid = threadIdx.x;
    const int s   = blockIdx.x * 64 + (tid >> 2);
    const int sub = tid & 3;
    const int nsl = sel ? NSL_A : NSL_S;
    const float* base = sel ? g_pt4_a : g_pt4_s;

    float m0 = FLT_BIG, m1 = FLT_BIG, m2 = FLT_BIG, m3 = FLT_BIG;
    for (int k = sub; k < nsl; k += 4) {
        float4 v = *(const float4*)(base + (k * NSMP + s) * 4);
        ins4(v.x, m0, m1, m2, m3);
        ins4(v.y, m0, m1, m2, m3);
        ins4(v.z, m0, m1, m2, m3);
        ins4(v.w, m0, m1, m2, m3);
    }
    #pragma unroll
    for (int off = 2; off >= 1; off >>= 1) {
        float n0 = __shfl_down_sync(0xffffffffu, m0, off);
        float n1 = __shfl_down_sync(0xffffffffu, m1, off);
        float n2 = __shfl_down_sync(0xffffffffu, m2, off);
        float n3 = __shfl_down_sync(0xffffffffu, m3, off);
        ins4(n0, m0, m1, m2, m3);
        ins4(n1, m0, m1, m2, m3);
        ins4(n2, m0, m1, m2, m3);
        ins4(n3, m0, m1, m2, m3);
    }
    if (sub == 0) {
        g_tail[sel][s] = 0.25f * ((m0 + m1) + (m2 + m3));
        g_sq[sel][s]   = (m0 * m0 + m1 * m1) + (m2 * m2 + m3 * m3);
        g_cnt[sel][s]  = 0;
    }
}

// ---------------- rank counts (stable, matching lax.top_k ties) ------------
// grid: (SCHUNK, 2, 16): z splits j into 128-chunks; int atomic partial counts
__global__ void rank_kernel() {
    __shared__ __align__(16) float tj_s[128];
    const int sel = blockIdx.y;
    const int tid = threadIdx.x;
    const int jbase = blockIdx.z * 128;
    if (tid < 128) tj_s[tid] = g_tail[sel][jbase + tid];
    __syncthreads();

    const int i  = blockIdx.x * TPB + tid;
    const int ti = __float_as_int(g_tail[sel][i]);   // positive: int order == fp order
    int cnt = 0;
    #pragma unroll
    for (int jj = 0; jj < 128; jj += 4) {
        float4 v = *(const float4*)(tj_s + jj);
        int t0 = __float_as_int(v.x), t1 = __float_as_int(v.y);
        int t2 = __float_as_int(v.z), t3 = __float_as_int(v.w);
        cnt += (t0 > ti) || (t0 == ti && (jbase + jj)     < i);
        cnt += (t1 > ti) || (t1 == ti && (jbase + jj + 1) < i);
        cnt += (t2 > ti) || (t2 == ti && (jbase + jj + 2) < i);
        cnt += (t3 > ti) || (t3 == ti && (jbase + jj + 3) < i);
    }
    if (cnt) atomicAdd(&g_cnt[sel][i], cnt);
}

// ---------------- final combine (deterministic fixed-order reduce) ---------
__global__ void combine_kernel(float* __restrict__ out) {
    __shared__ float red[TPB];
    const int tid = threadIdx.x;
    float acc = 0.0f;
    for (int i = tid; i < NSMP; i += TPB) {
        if (g_cnt[0][i] < FARK) acc += g_sq[0][i];
        if (g_cnt[1][i] < FARK) acc += g_sq[1][i];
    }
    red[tid] = acc;
    __syncthreads();
    for (int st = TPB / 2; st > 0; st >>= 1) {
        if (tid < st) red[tid] += red[tid + st];
        __syncthreads();
    }
    if (tid == 0) {
        float ss = 0.f, sa = 0.f;
        #pragma unroll
        for (int b = 0; b < 16; b++)  ss += g_size_part[b];
        #pragma unroll
        for (int b = 16; b < 32; b++) sa += g_size_part[b];
        out[0] = ss / (float)NLAT + sa / (float)NLAT
               + red[0] / (float)(FARK * TAILK);
    }
}

// ---------------- launch ----------------------------------------------------
extern "C" void kernel_launch(void* const* d_in, const int* in_sizes, int n_in,
                              void* d_out, int out_size) {
    const float* lat_s = (const float*)d_in[0];   // latent_states   [8192,64]
    const float* lat_a = (const float*)d_in[1];   // latent_actions  [8192,32]
    const float* smp_s = (const float*)d_in[2];   // state samples   [2048,64]
    const float* smp_a = (const float*)d_in[3];   // action samples  [2048,32]
    float* out = (float*)d_out;

    cov_partial_kernel<<<dim3(SCHUNK, NSL_S + NSL_A + NSL_Z), TPB>>>(smp_s, lat_s, smp_a, lat_a);
    cov_merge_kernel<<<dim3(NSMP / 64, 2), TPB>>>();
    rank_kernel<<<dim3(SCHUNK, 2, 16), TPB>>>();
    combine_kernel<<<1, TPB>>>(out);
}

// round 6
// speedup vs baseline: 1.7481x; 1.0038x over previous
#include <cuda_runtime.h>
#include <cuda_bf16.h>

// Problem constants
#define NLAT   8192
#define NSMP   2048
#define ES     64
#define EA     32
#define TAILK  4
#define FARK   64
#define TPB    256
#define SCHUNK (NSMP / TPB)     // 8 sample chunks
#define NSL_S  45               // latent slices, states
#define NSL_A  25               // latent slices, actions
#define NSL_Z  4                // size-loss block rows
// 8*(45+25+4) = 592 blocks = exactly 2 waves at occupancy 2
#define FLT_BIG 3.402823466e+38f

// ---------------- scratch (device globals; no allocation allowed) ----------
__device__ float g_pt4_s[NSL_S * NSMP * 4];   // [slice][sample][4]
__device__ float g_pt4_a[NSL_A * NSMP * 4];
__device__ float g_tail[2][NSMP];
__device__ float g_sq[2][NSMP];
__device__ int   g_cnt[2][NSMP];
__device__ float g_size_part[NSL_Z * 8];

// branchless sorted insert: keep m0<=m1<=m2<=m3 smallest
__device__ __forceinline__ void ins4(float d, float& m0, float& m1, float& m2, float& m3) {
    float lo, hi;
    lo = fminf(m0, d);  hi = fmaxf(m0, d);  m0 = lo;
    lo = fminf(m1, hi); hi = fmaxf(m1, hi); m1 = lo;
    lo = fminf(m2, hi); hi = fmaxf(m2, hi); m2 = lo;
    m3 = fminf(m3, hi);
}

// ---------------- size loss partials (runs inside the cov launch) ----------
template<int E>
__device__ __forceinline__ float size_accum(const float* __restrict__ lat, int r0, int nrows, int tid) {
    float acc = 0.0f;
    for (int r = r0 + tid; r < r0 + nrows; r += TPB) {
        const float* row = lat + r * E;
        float a0 = 0.f, a1 = 0.f, a2 = 0.f, a3 = 0.f;
        #pragma unroll
        for (int k = 0; k < E; k += 4) {
            float4 v = *(const float4*)(row + k);
            a0 += fabsf(v.x); a1 += fabsf(v.y); a2 += fabsf(v.z); a3 += fabsf(v.w);
        }
        float n = (a0 + a1) + (a2 + a3);
        float viol = fmaxf(n - 1.0f, 0.0f);
        acc += viol * viol;
    }
    return acc;
}

__device__ void size_body(const float* __restrict__ lat_s,
                          const float* __restrict__ lat_a, int b, float* red) {
    const int tid = threadIdx.x;
    // 32 blocks: 16 for states (512 rows each), 16 for actions (512 rows each)
    float acc = (b < 16) ? size_accum<ES>(lat_s, b * 512, 512, tid)
                         : size_accum<EA>(lat_a, (b - 16) * 512, 512, tid);
    red[tid] = acc;
    __syncthreads();
    for (int st = TPB / 2; st > 0; st >>= 1) {
        if (tid < st) red[tid] += red[tid + st];
        __syncthreads();
    }
    if (tid == 0) g_size_part[b] = red[0];
}

// ---------------- coverage partial top-4 (FFMA-imm, latent-pair unroll) ----
// d  = fmaf(lat, -0.5, q*0.5)  -> FFMA-imm rt=1
// acc= fmaf(|d|, 2.0, acc)     -> FFMA-imm rt=1; exact rescale, bit-identical
template<int E, int TN, int NSL>
__device__ __forceinline__ void cov_body(const float* __restrict__ samples,
                                         const float* __restrict__ latents,
                                         int slice, float* tile, float* out4) {
    const int tid = threadIdx.x;
    const int s   = blockIdx.x * TPB + tid;

    constexpr int base = NLAT / NSL;
    constexpr int rem  = NLAT % NSL;
    const int start = slice * base + (slice < rem ? slice : rem);
    const int len   = base + (slice < rem ? 1 : 0);

    // sample row * 0.5 -> registers (exact)
    float qh[E];
    #pragma unroll
    for (int k = 0; k < E; k += 4) {
        float4 v = *(const float4*)(samples + s * E + k);
        qh[k] = 0.5f * v.x; qh[k + 1] = 0.5f * v.y;
        qh[k + 2] = 0.5f * v.z; qh[k + 3] = 0.5f * v.w;
    }

    float m0 = FLT_BIG, m1 = FLT_BIG, m2 = FLT_BIG, m3 = FLT_BIG;

    for (int t0 = 0; t0 < len; t0 += TN) {
        const int tn = (len - t0 < TN) ? (len - t0) : TN;
        __syncthreads();
        const float4* src = (const float4*)(latents + (start + t0) * E);
        float4* dst = (float4*)tile;
        for (int i = tid; i < tn * (E / 4); i += TPB) dst[i] = src[i];
        __syncthreads();

        int n = 0;
        #pragma unroll 1
        for (; n + 2 <= tn; n += 2) {
            const float4* lrA = (const float4*)(tile + n * E);
            const float4* lrB = (const float4*)(tile + (n + 1) * E);
            float a0 = 0.f, a1 = 0.f, a2 = 0.f, a3 = 0.f;
            float b0 = 0.f, b1 = 0.f, b2 = 0.f, b3 = 0.f;
            #pragma unroll
            for (int k = 0; k < E / 4; k++) {
                float4 va = lrA[k];
                float d0 = fmaf(va.x, -0.5f, qh[4 * k]);
                float d1 = fmaf(va.y, -0.5f, qh[4 * k + 1]);
                float d2 = fmaf(va.z, -0.5f, qh[4 * k + 2]);
                float d3 = fmaf(va.w, -0.5f, qh[4 * k + 3]);
                a0 = fmaf(fabsf(d0), 2.0f, a0);
                a1 = fmaf(fabsf(d1), 2.0f, a1);
                a2 = fmaf(fabsf(d2), 2.0f, a2);
                a3 = fmaf(fabsf(d3), 2.0f, a3);
                float4 vb = lrB[k];
                float e0 = fmaf(vb.x, -0.5f, qh[4 * k]);
                float e1 = fmaf(vb.y, -0.5f, qh[4 * k + 1]);
                float e2 = fmaf(vb.z, -0.5f, qh[4 * k + 2]);
                float e3 = fmaf(vb.w, -0.5f, qh[4 * k + 3]);
                b0 = fmaf(fabsf(e0), 2.0f, b0);
                b1 = fmaf(fabsf(e1), 2.0f, b1);
                b2 = fmaf(fabsf(e2), 2.0f, b2);
                b3 = fmaf(fabsf(e3), 2.0f, b3);
            }
            float dA = (a0 + a1) + (a2 + a3);
            float dB = (b0 + b1) + (b2 + b3);
            ins4(dA, m0, m1, m2, m3);
            ins4(dB, m0, m1, m2, m3);
        }
        if (n < tn) {   // odd epilogue
            const float4* lr = (const float4*)(tile + n * E);
            float a0 = 0.f, a1 = 0.f, a2 = 0.f, a3 = 0.f;
            #pragma unroll
            for (int k = 0; k < E / 4; k++) {
                float4 v = lr[k];
                float d0 = fmaf(v.x, -0.5f, qh[4 * k]);
                float d1 = fmaf(v.y, -0.5f, qh[4 * k + 1]);
                float d2 = fmaf(v.z, -0.5f, qh[4 * k + 2]);
                float d3 = fmaf(v.w, -0.5f, qh[4 * k + 3]);
                a0 = fmaf(fabsf(d0), 2.0f, a0);
                a1 = fmaf(fabsf(d1), 2.0f, a1);
                a2 = fmaf(fabsf(d2), 2.0f, a2);
                a3 = fmaf(fabsf(d3), 2.0f, a3);
            }
            ins4((a0 + a1) + (a2 + a3), m0, m1, m2, m3);
        }
    }
    *(float4*)(out4 + (slice * NSMP + s) * 4) = make_float4(m0, m1, m2, m3);
}

// grid: (SCHUNK, NSL_S + NSL_A + NSL_Z)
__global__ void __launch_bounds__(TPB, 2)
cov_partial_kernel(const float* __restrict__ smp_s, const float* __restrict__ lat_s,
                   const float* __restrict__ smp_a, const float* __restrict__ lat_a) {
    __shared__ __align__(16) float tile[8192];   // 32 KB
    const int y = blockIdx.y;
    if (y < NSL_S)
        cov_body<ES, 128, NSL_S>(smp_s, lat_s, y, tile, g_pt4_s);
    else if (y < NSL_S + NSL_A)
        cov_body<EA, 256, NSL_A>(smp_a, lat_a, y - NSL_S, tile, g_pt4_a);
    else
        size_body(lat_s, lat_a, (y - NSL_S - NSL_A) * 8 + blockIdx.x, tile);
}

// ---------------- merge partial top-4 across slices ------------------------
// 4 threads per sample, shfl combine. grid: (NSMP/64, 2)
__global__ void cov_merge_kernel() {
    const int sel = blockIdx.y;
    const int tid = threadIdx.x;
    const int s   = blockIdx.x * 64 + (tid >> 2);
    const int sub = tid & 3;
    const int nsl = sel ? NSL_A : NSL_S;
    const float* base = sel ? g_pt4_a : g_pt4_s;

    float m0 = FLT_BIG, m1 = FLT_BIG, m2 = FLT_BIG, m3 = FLT_BIG;
    for (int k = sub; k < nsl; k += 4) {
        float4 v = *(const float4*)(base + (k * NSMP + s) * 4);
        ins4(v.x, m0, m1, m2, m3);
        ins4(v.y, m0, m1, m2, m3);
        ins4(v.z, m0, m1, m2, m3);
        ins4(v.w, m0, m1, m2, m3);
    }
    #pragma unroll
    for (int off = 2; off >= 1; off >>= 1) {
        float n0 = __shfl_down_sync(0xffffffffu, m0, off);
        float n1 = __shfl_down_sync(0xffffffffu, m1, off);
        float n2 = __shfl_down_sync(0xffffffffu, m2, off);
        float n3 = __shfl_down_sync(0xffffffffu, m3, off);
        ins4(n0, m0, m1, m2, m3);
        ins4(n1, m0, m1, m2, m3);
        ins4(n2, m0, m1, m2, m3);
        ins4(n3, m0, m1, m2, m3);
    }
    if (sub == 0) {
        g_tail[sel][s] = 0.25f * ((m0 + m1) + (m2 + m3));
        g_sq[sel][s]   = (m0 * m0 + m1 * m1) + (m2 * m2 + m3 * m3);
        g_cnt[sel][s]  = 0;
    }
}

// ---------------- rank counts (stable, matching lax.top_k ties) ------------
// grid: (SCHUNK, 2, 16): z splits j into 128-chunks; int atomic partial counts
__global__ void rank_kernel() {
    __shared__ __align__(16) float tj_s[128];
    const int sel = blockIdx.y;
    const int tid = threadIdx.x;
    const int jbase = blockIdx.z * 128;
    if (tid < 128) tj_s[tid] = g_tail[sel][jbase + tid];
    __syncthreads();

    const int i  = blockIdx.x * TPB + tid;
    const int ti = __float_as_int(g_tail[sel][i]);   // positive: int order == fp order
    int cnt = 0;
    #pragma unroll
    for (int jj = 0; jj < 128; jj += 4) {
        float4 v = *(const float4*)(tj_s + jj);
        int t0 = __float_as_int(v.x), t1 = __float_as_int(v.y);
        int t2 = __float_as_int(v.z), t3 = __float_as_int(v.w);
        cnt += (t0 > ti) || (t0 == ti && (jbase + jj)     < i);
        cnt += (t1 > ti) || (t1 == ti && (jbase + jj + 1) < i);
        cnt += (t2 > ti) || (t2 == ti && (jbase + jj + 2) < i);
        cnt += (t3 > ti) || (t3 == ti && (jbase + jj + 3) < i);
    }
    if (cnt) atomicAdd(&g_cnt[sel][i], cnt);
}

// ---------------- final combine (deterministic fixed-order reduce) ---------
__global__ void combine_kernel(float* __restrict__ out) {
    __shared__ float red[TPB];
    const int tid = threadIdx.x;
    float acc = 0.0f;
    for (int i = tid; i < NSMP; i += TPB) {
        if (g_cnt[0][i] < FARK) acc += g_sq[0][i];
        if (g_cnt[1][i] < FARK) acc += g_sq[1][i];
    }
    red[tid] = acc;
    __syncthreads();
    for (int st = TPB / 2; st > 0; st >>= 1) {
        if (tid < st) red[tid] += red[tid + st];
        __syncthreads();
    }
    if (tid == 0) {
        float ss = 0.f, sa = 0.f;
        #pragma unroll
        for (int b = 0; b < 16; b++)  ss += g_size_part[b];
        #pragma unroll
        for (int b = 16; b < 32; b++) sa += g_size_part[b];
        out[0] = ss / (float)NLAT + sa / (float)NLAT
               + red[0] / (float)(FARK * TAILK);
    }
}

// ---------------- launch ----------------------------------------------------
extern "C" void kernel_launch(void* const* d_in, const int* in_sizes, int n_in,
                              void* d_out, int out_size) {
    const float* lat_s = (const float*)d_in[0];   // latent_states   [8192,64]
    const float* lat_a = (const float*)d_in[1];   // latent_actions  [8192,32]
    const float* smp_s = (const float*)d_in[2];   // state samples   [2048,64]
    const float* smp_a = (const float*)d_in[3];   // action samples  [2048,32]
    float* out = (float*)d_out;

    cov_partial_kernel<<<dim3(SCHUNK, NSL_S + NSL_A + NSL_Z), TPB>>>(smp_s, lat_s, smp_a, lat_a);
    cov_merge_kernel<<<dim3(NSMP / 64, 2), TPB>>>();
    rank_kernel<<<dim3(SCHUNK, 2, 16), TPB>>>();
    combine_kernel<<<1, TPB>>>(out);
}